// round 1
// baseline (speedup 1.0000x reference)
#include <cuda_runtime.h>
#include <cstdint>

// Problem constants (fixed by the dataset)
#define E_CNT   800000
#define N_CNT   50000
#define NGR     16
#define NLAY    3

// ---------------- scratch (device globals; no allocations allowed) ----------
__device__ float g_ea[E_CNT * 64];            // edge features (per-layer output)
__device__ float g_hcur[N_CNT * 64];          // node features h
__device__ float g_hsum[N_CNT * 64];          // scatter-sum accumulator
__device__ int   g_cnt_node[N_CNT];           // in-degree per node
__device__ int   g_cnt_ng[NGR];               // nodes per graph
__device__ int   g_cnt_eg[NGR];               // edges per graph
__device__ float g_gnsum[(NLAY + 1) * NGR * 64];  // node pools (sums)
__device__ float g_gesum[(NLAY + 1) * NGR * 64];  // edge pools (sums)

// ---------------- small PTX helpers -----------------------------------------
__device__ __forceinline__ unsigned long long dupf(float x) {
    unsigned long long r;
    asm("mov.b64 %0, {%1,%1};" : "=l"(r) : "f"(x));
    return r;
}
__device__ __forceinline__ void unpack2(unsigned long long p, float& lo, float& hi) {
    asm("mov.b64 {%0,%1}, %2;" : "=f"(lo), "=f"(hi) : "l"(p));
}
__device__ __forceinline__ void fma2(unsigned long long& d, unsigned long long a,
                                     unsigned long long b) {
    asm("fma.rn.f32x2 %0, %1, %2, %0;" : "+l"(d) : "l"(a), "l"(b));
}
__device__ __forceinline__ void red4(float* p, float4 v) {
    asm volatile("red.global.add.v4.f32 [%0], {%1,%2,%3,%4};"
                 :: "l"(p), "f"(v.x), "f"(v.y), "f"(v.z), "f"(v.w) : "memory");
}

// ---------------- init: zero accumulators ------------------------------------
__global__ void k_init() {
    int t = blockIdx.x * blockDim.x + threadIdx.x;
    int stride = gridDim.x * blockDim.x;
    for (int i = t; i < N_CNT * 64; i += stride) g_hsum[i] = 0.f;
    for (int i = t; i < N_CNT; i += stride) g_cnt_node[i] = 0;
    for (int i = t; i < (NLAY + 1) * NGR * 64; i += stride) {
        g_gnsum[i] = 0.f;
        g_gesum[i] = 0.f;
    }
    for (int i = t; i < NGR; i += stride) { g_cnt_ng[i] = 0; g_cnt_eg[i] = 0; }
}

// ---------------- nodes-per-graph counts --------------------------------------
__global__ void k_node_cnt(const int* __restrict__ batch) {
    int t = blockIdx.x * blockDim.x + threadIdx.x;
    if (t < N_CNT) atomicAdd(&g_cnt_ng[batch[t]], 1);
}

// ---------------- layer-0 pooling + degree counts ------------------------------
// h_sum += edge_attr scattered by col; ge_sum[0] += edge_attr by graph; counts.
__global__ void k_pool0(const float* __restrict__ edge_attr,
                        const int* __restrict__ eidx,
                        const int* __restrict__ eb) {
    int t = blockIdx.x * blockDim.x + threadIdx.x;   // E*16 threads
    int e = t >> 4, c4 = t & 15;
    float4 v = *(const float4*)(edge_attr + e * 64 + c4 * 4);
    int c = eidx[E_CNT + e];
    int g = eb[e];
    red4(&g_hsum[c * 64 + c4 * 4], v);
    red4(&g_gesum[g * 64 + c4 * 4], v);
    if (c4 == 0) {
        atomicAdd(&g_cnt_node[c], 1);
        atomicAdd(&g_cnt_eg[g], 1);
    }
}

// ---------------- finalize h = h_sum / max(deg,1); pool to gn; zero h_sum ------
__global__ void k_finalize(int li, const int* __restrict__ batch) {
    int t = blockIdx.x * blockDim.x + threadIdx.x;   // N*16 threads
    int v = t >> 4, c4 = t & 15;
    float4 s = *(const float4*)(g_hsum + v * 64 + c4 * 4);
    float inv = 1.f / fmaxf((float)g_cnt_node[v], 1.f);
    float4 h;
    h.x = s.x * inv; h.y = s.y * inv; h.z = s.z * inv; h.w = s.w * inv;
    *(float4*)(g_hcur + v * 64 + c4 * 4) = h;
    red4(&g_gnsum[li * NGR * 64 + batch[v] * 64 + c4 * 4], h);
    float4 z = {0.f, 0.f, 0.f, 0.f};
    *(float4*)(g_hsum + v * 64 + c4 * 4) = z;
}

// ---------------- fused edge MLP + scatter -------------------------------------
// Per block: 64 edges. A = [h[row] | ea] (64x128) in SMEM; GEMM1 (->128, ReLU)
// into SMEM; GEMM2 (->64); epilogue: store ea, red4 to h_sum and ge_sum[l+1].
// f32x2 packed FMA throughout.
#define TE 64
#define SMEM_MLP_BYTES ((64 * 132 + 32 * 128 + 128 * 68) * 4 + 3 * 64 * 4)

__global__ void __launch_bounds__(256, 2)
k_mlp(const float* __restrict__ edge_attr,
      const int* __restrict__ eidx, const int* __restrict__ eb,
      const float* __restrict__ W1, const float* __restrict__ b1,
      const float* __restrict__ W2, const float* __restrict__ b2,
      int layer) {
    extern __shared__ float smem[];
    float* sA  = smem;                       // [64][132]
    float* sW1 = smem + 64 * 132;            // [32][128] (K-chunk of W1)
    float* sW2 = sW1 + 32 * 128;             // [128][68] (full W2, padded)
    int* sRow = (int*)(sW2 + 128 * 68);
    int* sCol = sRow + 64;
    int* sGB  = sCol + 64;

    const float* eain = (layer == 0) ? edge_attr : g_ea;
    float* geout = g_gesum + (layer + 1) * NGR * 64;

    const int tid = threadIdx.x;
    const int e0 = blockIdx.x * TE;
    const int eg = tid >> 4;                 // 16 groups of 4 edges
    const int cg = tid & 15;

    if (tid < 64)       sRow[tid]       = eidx[e0 + tid];
    else if (tid < 128) sCol[tid - 64]  = eidx[E_CNT + e0 + (tid - 64)];
    else if (tid < 192) sGB[tid - 128]  = eb[e0 + (tid - 128)];

    // load full W2 [128][64] -> stride 68
    #pragma unroll
    for (int i = 0; i < 8; ++i) {
        int f = tid + i * 256;               // float4 id 0..2047
        int r = f >> 4, c4 = f & 15;
        *(float4*)&sW2[r * 68 + c4 * 4] = *(const float4*)(W2 + r * 64 + c4 * 4);
    }
    __syncthreads();

    // gather A tile: cols [0,64) = h[row[e]], [64,128) = ea[e]
    #pragma unroll
    for (int i = 0; i < 8; ++i) {
        int f = tid + i * 256;               // float4 id 0..2047
        int e = f >> 5, part = f & 31;
        float4 v;
        if (part < 16) v = *(const float4*)(g_hcur + sRow[e] * 64 + part * 4);
        else           v = *(const float4*)(eain + (e0 + e) * 64 + (part - 16) * 4);
        *(float4*)&sA[e * 132 + part * 4] = v;
    }
    __syncthreads();

    // ---- GEMM1: hid[64][128] = A @ W1, 4 K-chunks of 32
    unsigned long long acc1[4][4];
    #pragma unroll
    for (int i = 0; i < 4; ++i)
        #pragma unroll
        for (int j = 0; j < 4; ++j) acc1[i][j] = 0ull;

    for (int kc = 0; kc < 4; ++kc) {
        #pragma unroll
        for (int i = 0; i < 4; ++i) {
            int f = tid + i * 256;           // float4 id 0..1023
            int r = f >> 5, c4 = f & 31;
            *(float4*)&sW1[r * 128 + c4 * 4] =
                *(const float4*)(W1 + (kc * 32 + r) * 128 + c4 * 4);
        }
        __syncthreads();
        #pragma unroll
        for (int k = 0; k < 32; ++k) {
            unsigned long long a[4];
            #pragma unroll
            for (int i = 0; i < 4; ++i)
                a[i] = dupf(sA[(eg * 4 + i) * 132 + kc * 32 + k]);
            const ulonglong2 w0 = *(const ulonglong2*)&sW1[k * 128 + cg * 8];
            const ulonglong2 w1 = *(const ulonglong2*)&sW1[k * 128 + cg * 8 + 4];
            #pragma unroll
            for (int i = 0; i < 4; ++i) {
                fma2(acc1[i][0], a[i], w0.x);
                fma2(acc1[i][1], a[i], w0.y);
                fma2(acc1[i][2], a[i], w1.x);
                fma2(acc1[i][3], a[i], w1.y);
            }
        }
        __syncthreads();
    }

    // bias + ReLU, write hid back into sA
    float b1r[8];
    #pragma unroll
    for (int j = 0; j < 8; ++j) b1r[j] = b1[cg * 8 + j];
    #pragma unroll
    for (int i = 0; i < 4; ++i) {
        #pragma unroll
        for (int j = 0; j < 4; ++j) {
            float lo, hi;
            unpack2(acc1[i][j], lo, hi);
            lo = fmaxf(lo + b1r[2 * j], 0.f);
            hi = fmaxf(hi + b1r[2 * j + 1], 0.f);
            float2 p = {lo, hi};
            *(float2*)&sA[(eg * 4 + i) * 132 + cg * 8 + 2 * j] = p;
        }
    }
    __syncthreads();

    // ---- GEMM2: out[64][64] = hid @ W2
    unsigned long long acc2[4][2];
    #pragma unroll
    for (int i = 0; i < 4; ++i) { acc2[i][0] = 0ull; acc2[i][1] = 0ull; }

    #pragma unroll 8
    for (int k = 0; k < 128; ++k) {
        unsigned long long a[4];
        #pragma unroll
        for (int i = 0; i < 4; ++i)
            a[i] = dupf(sA[(eg * 4 + i) * 132 + k]);
        const ulonglong2 w = *(const ulonglong2*)&sW2[k * 68 + cg * 4];
        #pragma unroll
        for (int i = 0; i < 4; ++i) {
            fma2(acc2[i][0], a[i], w.x);
            fma2(acc2[i][1], a[i], w.y);
        }
    }

    // epilogue: +b2, store ea, scatter to node sums and graph edge pool
    float b2r[4];
    #pragma unroll
    for (int j = 0; j < 4; ++j) b2r[j] = b2[cg * 4 + j];
    #pragma unroll
    for (int i = 0; i < 4; ++i) {
        int el = eg * 4 + i;
        int e = e0 + el;
        float4 v;
        unpack2(acc2[i][0], v.x, v.y);
        unpack2(acc2[i][1], v.z, v.w);
        v.x += b2r[0]; v.y += b2r[1]; v.z += b2r[2]; v.w += b2r[3];
        *(float4*)(g_ea + e * 64 + cg * 4) = v;
        red4(&g_hsum[sCol[el] * 64 + cg * 4], v);
        red4(&geout[sGB[el] * 64 + cg * 4], v);
    }
}

// ---------------- output head: one block per graph ----------------------------
__global__ void k_head(const float* __restrict__ Wo1, const float* __restrict__ bo1,
                       const float* __restrict__ Wo2, const float* __restrict__ bo2,
                       const float* __restrict__ Wo3, const float* __restrict__ bo3,
                       float* __restrict__ out) {
    __shared__ float aa[512];
    __shared__ float s1[128];
    __shared__ float s2[128];
    int g = blockIdx.x;
    int tid = threadIdx.x;
    float ninv = 1.f / fmaxf((float)g_cnt_ng[g], 1.f);
    float einv = 1.f / fmaxf((float)g_cnt_eg[g], 1.f);
    for (int i = tid; i < 512; i += 128) {
        float v;
        if (i < 256) {
            v = g_gnsum[(i >> 6) * NGR * 64 + g * 64 + (i & 63)] * ninv;
            out[g * 256 + i] = v;
        } else {
            int c = i - 256;
            v = g_gesum[(c >> 6) * NGR * 64 + g * 64 + (c & 63)] * einv;
            out[4096 + g * 256 + c] = v;
        }
        aa[i] = v;
    }
    __syncthreads();
    {
        float s = bo1[tid];
        for (int k = 0; k < 512; ++k) s = fmaf(aa[k], Wo1[k * 128 + tid], s);
        s1[tid] = fmaxf(s, 0.f);
    }
    __syncthreads();
    {
        float s = bo2[tid];
        for (int k = 0; k < 128; ++k) s = fmaf(s1[k], Wo2[k * 128 + tid], s);
        s2[tid] = fmaxf(s, 0.f);
    }
    __syncthreads();
    if (tid < 32) {
        float s = bo3[tid];
        for (int k = 0; k < 128; ++k) s = fmaf(s2[k], Wo3[k * 32 + tid], s);
        out[8192 + g * 32 + tid] = s;
    }
}

// ---------------- launcher ----------------------------------------------------
extern "C" void kernel_launch(void* const* d_in, const int* in_sizes, int n_in,
                              void* d_out, int out_size) {
    const float* edge_attr = (const float*)d_in[1];
    const int*   eidx      = (const int*)d_in[3];
    const int*   batch     = (const int*)d_in[4];
    const int*   eb        = (const int*)d_in[5];
    const float* W1s       = (const float*)d_in[6];
    const float* b1s       = (const float*)d_in[7];
    const float* W2s       = (const float*)d_in[8];
    const float* b2s       = (const float*)d_in[9];
    const float* Wo1       = (const float*)d_in[10];
    const float* bo1       = (const float*)d_in[11];
    const float* Wo2       = (const float*)d_in[12];
    const float* bo2       = (const float*)d_in[13];
    const float* Wo3       = (const float*)d_in[14];
    const float* bo3       = (const float*)d_in[15];
    float* out = (float*)d_out;

    cudaFuncSetAttribute((const void*)k_mlp,
                         cudaFuncAttributeMaxDynamicSharedMemorySize,
                         SMEM_MLP_BYTES);

    k_init<<<2048, 256>>>();
    k_node_cnt<<<(N_CNT + 255) / 256, 256>>>(batch);
    k_pool0<<<(E_CNT * 16) / 256, 256>>>(edge_attr, eidx, eb);
    k_finalize<<<(N_CNT * 16) / 256, 256>>>(0, batch);

    for (int l = 0; l < NLAY; ++l) {
        k_mlp<<<E_CNT / TE, 256, SMEM_MLP_BYTES>>>(
            edge_attr, eidx, eb,
            W1s + l * 128 * 128, b1s + l * 128,
            W2s + l * 128 * 64, b2s + l * 64, l);
        k_finalize<<<(N_CNT * 16) / 256, 256>>>(l + 1, batch);
    }

    k_head<<<NGR, 128>>>(Wo1, bo1, Wo2, bo2, Wo3, bo3, out);
}

// round 3
// speedup vs baseline: 1.3990x; 1.3990x over previous
#include <cuda_runtime.h>
#include <cstdint>

// Problem constants (fixed by the dataset)
#define E_CNT   800000
#define N_CNT   50000
#define NGR     16
#define NLAY    3
#define TE      128      // edges per k_mlp block

// ---------------- scratch (device globals; no allocations allowed) ----------
__device__ float g_ea[E_CNT * 64];            // edge features (per-layer output)
__device__ float g_hcur[N_CNT * 64];          // node features h
__device__ float g_hsum[N_CNT * 64];          // scatter-sum accumulator
__device__ int   g_cnt_node[N_CNT];           // in-degree per node
__device__ int   g_cnt_ng[NGR];               // nodes per graph
__device__ int   g_cnt_eg[NGR];               // edges per graph
__device__ float g_gnsum[(NLAY + 1) * NGR * 64];  // node pools (sums)
__device__ float g_gesum[(NLAY + 1) * NGR * 64];  // edge pools (sums)

// ---------------- PTX helpers ------------------------------------------------
__device__ __forceinline__ void red4(float* p, float4 v) {
    asm volatile("red.global.add.v4.f32 [%0], {%1,%2,%3,%4};"
                 :: "l"(p), "f"(v.x), "f"(v.y), "f"(v.z), "f"(v.w) : "memory");
}
__device__ __forceinline__ void red2(float* p, float2 v) {
    asm volatile("red.global.add.v2.f32 [%0], {%1,%2};"
                 :: "l"(p), "f"(v.x), "f"(v.y) : "memory");
}
__device__ __forceinline__ void red1(float* p, float v) {
    asm volatile("red.global.add.f32 [%0], %1;" :: "l"(p), "f"(v) : "memory");
}
// rounded f32 -> tf32 (keeps value as b32 with low mantissa cleared)
__device__ __forceinline__ uint32_t f2tf(float x) {
    uint32_t r;
    asm("cvt.rna.tf32.f32 %0, %1;" : "=r"(r) : "f"(x));
    return r;
}
__device__ __forceinline__ void split_tf(float x, uint32_t& hi, uint32_t& lo) {
    hi = f2tf(x);
    lo = f2tf(x - __uint_as_float(hi));
}
// m16n8k8 tf32 mma, row.col, f32 accumulate. Fragment map (PTX ISA):
//  A: a0=(g,t) a1=(g+8,t) a2=(g,t+4) a3=(g+8,t+4)   [g=lane>>2, t=lane&3]
//  B: b0=(k=t,n=g) b1=(k=t+4,n=g)
//  C: c0=(g,2t) c1=(g,2t+1) c2=(g+8,2t) c3=(g+8,2t+1)
__device__ __forceinline__ void mma_tf32(float* d, const uint32_t* a,
                                         uint32_t b0, uint32_t b1) {
    asm volatile(
        "mma.sync.aligned.m16n8k8.row.col.f32.tf32.tf32.f32 "
        "{%0,%1,%2,%3}, {%4,%5,%6,%7}, {%8,%9}, {%0,%1,%2,%3};"
        : "+f"(d[0]), "+f"(d[1]), "+f"(d[2]), "+f"(d[3])
        : "r"(a[0]), "r"(a[1]), "r"(a[2]), "r"(a[3]), "r"(b0), "r"(b1));
}

// ---------------- init: zero accumulators ------------------------------------
__global__ void k_init() {
    int t = blockIdx.x * blockDim.x + threadIdx.x;
    int stride = gridDim.x * blockDim.x;
    for (int i = t; i < N_CNT * 64; i += stride) g_hsum[i] = 0.f;
    for (int i = t; i < N_CNT; i += stride) g_cnt_node[i] = 0;
    for (int i = t; i < (NLAY + 1) * NGR * 64; i += stride) {
        g_gnsum[i] = 0.f;
        g_gesum[i] = 0.f;
    }
    for (int i = t; i < NGR; i += stride) { g_cnt_ng[i] = 0; g_cnt_eg[i] = 0; }
}

// ---------------- nodes-per-graph counts --------------------------------------
__global__ void k_node_cnt(const int* __restrict__ batch) {
    int t = blockIdx.x * blockDim.x + threadIdx.x;
    if (t < N_CNT) atomicAdd(&g_cnt_ng[batch[t]], 1);
}

// ---------------- layer-0 pooling + degree counts ------------------------------
// 16 edges per 256-thread block. edge_attr_batch is sorted -> <=2 graphs/block:
// accumulate graph-pool in SMEM, flush once (avoids L2-atomic serialization).
__global__ void k_pool0(const float* __restrict__ edge_attr,
                        const int* __restrict__ eidx,
                        const int* __restrict__ eb) {
    __shared__ float sP[128];
    __shared__ int sCnt[2];
    __shared__ int s_gmin;
    int tid = threadIdx.x;
    int e = blockIdx.x * 16 + (tid >> 4);
    int c4 = tid & 15;
    if (tid < 128) sP[tid] = 0.f;
    if (tid < 2) sCnt[tid] = 0;
    if (tid == 0) s_gmin = eb[blockIdx.x * 16];
    __syncthreads();

    float4 v = *(const float4*)(edge_attr + (size_t)e * 64 + c4 * 4);
    int c = eidx[E_CNT + e];
    int g = eb[e];
    red4(&g_hsum[(size_t)c * 64 + c4 * 4], v);
    if (c4 == 0) atomicAdd(&g_cnt_node[c], 1);

    int slot = g - s_gmin;
    if (slot < 2) {
        atomicAdd(&sP[slot * 64 + c4 * 4 + 0], v.x);
        atomicAdd(&sP[slot * 64 + c4 * 4 + 1], v.y);
        atomicAdd(&sP[slot * 64 + c4 * 4 + 2], v.z);
        atomicAdd(&sP[slot * 64 + c4 * 4 + 3], v.w);
        if (c4 == 0) atomicAdd(&sCnt[slot], 1);
    } else {
        red4(&g_gesum[g * 64 + c4 * 4], v);
        if (c4 == 0) atomicAdd(&g_cnt_eg[g], 1);
    }
    __syncthreads();
    if (tid < 32) {
        int sl = tid >> 4, cc = (tid & 15) * 4;
        int gg = s_gmin + sl;
        if (gg < NGR) {
            float4 p = *(float4*)&sP[sl * 64 + cc];
            if (p.x != 0.f || p.y != 0.f || p.z != 0.f || p.w != 0.f)
                red4(&g_gesum[gg * 64 + cc], p);
            if ((tid & 15) == 0 && sCnt[sl] > 0) atomicAdd(&g_cnt_eg[gg], sCnt[sl]);
        }
    }
}

// ---------------- finalize h = h_sum/max(deg,1); pool to gn; zero h_sum --------
// 16 nodes per 256-thread block; batch sorted -> SMEM pool accumulation.
__global__ void k_finalize(int li, const int* __restrict__ batch) {
    __shared__ float sP[128];
    __shared__ int s_gmin;
    int tid = threadIdx.x;
    int v = blockIdx.x * 16 + (tid >> 4);
    int c4 = tid & 15;
    if (tid < 128) sP[tid] = 0.f;
    if (tid == 0) s_gmin = batch[blockIdx.x * 16];
    __syncthreads();

    float4 s = *(float4*)(g_hsum + (size_t)v * 64 + c4 * 4);
    float inv = 1.f / fmaxf((float)g_cnt_node[v], 1.f);
    float4 h = {s.x * inv, s.y * inv, s.z * inv, s.w * inv};
    *(float4*)(g_hcur + (size_t)v * 64 + c4 * 4) = h;
    float4 z = {0.f, 0.f, 0.f, 0.f};
    *(float4*)(g_hsum + (size_t)v * 64 + c4 * 4) = z;

    int gb = batch[v];
    int slot = gb - s_gmin;
    if (slot < 2) {
        atomicAdd(&sP[slot * 64 + c4 * 4 + 0], h.x);
        atomicAdd(&sP[slot * 64 + c4 * 4 + 1], h.y);
        atomicAdd(&sP[slot * 64 + c4 * 4 + 2], h.z);
        atomicAdd(&sP[slot * 64 + c4 * 4 + 3], h.w);
    } else {
        red4(&g_gnsum[li * NGR * 64 + gb * 64 + c4 * 4], h);
    }
    __syncthreads();
    if (tid < 32) {
        int sl = tid >> 4, cc = (tid & 15) * 4;
        int gg = s_gmin + sl;
        if (gg < NGR) {
            float4 p = *(float4*)&sP[sl * 64 + cc];
            if (p.x != 0.f || p.y != 0.f || p.z != 0.f || p.w != 0.f)
                red4(&g_gnsum[li * NGR * 64 + gg * 64 + cc], p);
        }
    }
}

// ---------------- fused edge MLP (tf32x3 tensor cores) + scatter ---------------
// Block: 128 edges, 512 threads. SMEM: A/hid [128][132] (in place), W1 [128][132],
// W2 [128][68] (pads -> conflict-free fragment loads).
// tf32x3: per operand split hi/lo in registers (cvt.rna), accumulate
// Ahi*Bhi + Ahi*Blo + Alo*Bhi -> ~fp32 precision on tensor cores.
#define SMEM_MLP_BYTES ((16896 + 16896 + 8704 + 128 + 64 + 128) * 4 + 384 * 4)

__global__ void __launch_bounds__(512, 1)
k_mlp(const float* __restrict__ edge_attr,
      const int* __restrict__ eidx, const int* __restrict__ eb,
      const float* __restrict__ W1, const float* __restrict__ b1,
      const float* __restrict__ W2, const float* __restrict__ b2,
      int layer) {
    extern __shared__ float sm[];
    float* sA  = sm;                  // [128][132] A then hid (in place)
    float* sW1 = sm + 16896;          // [128][132]
    float* sW2 = sW1 + 16896;         // [128][68]
    float* sB1 = sW2 + 8704;          // [128]
    float* sB2 = sB1 + 128;           // [64]
    float* sGE = sB2 + 64;            // [2][64]
    int* sRow = (int*)(sGE + 128);
    int* sCol = sRow + 128;
    int* sGB  = sCol + 128;

    const float* ea_in = (layer == 0) ? edge_attr : g_ea;
    float* geout = g_gesum + (layer + 1) * NGR * 64;

    const int tid = threadIdx.x;
    const int e0 = blockIdx.x * TE;

    if (tid < 128) { sRow[tid] = eidx[e0 + tid]; sB1[tid] = b1[tid]; sGE[tid] = 0.f; }
    else if (tid < 256) { sCol[tid - 128] = eidx[E_CNT + e0 + tid - 128]; }
    else if (tid < 384) { sGB[tid - 256] = eb[e0 + tid - 256]; }
    else if (tid < 448) { sB2[tid - 384] = b2[tid - 384]; }

    #pragma unroll
    for (int i = 0; i < 8; ++i) {     // W1: 4096 float4
        int f = tid + i * 512; int r = f >> 5, c = f & 31;
        *(float4*)&sW1[r * 132 + c * 4] = *(const float4*)(W1 + f * 4);
    }
    #pragma unroll
    for (int i = 0; i < 4; ++i) {     // W2: 2048 float4
        int f = tid + i * 512; int r = f >> 4, c = f & 15;
        *(float4*)&sW2[r * 68 + c * 4] = *(const float4*)(W2 + f * 4);
    }
    __syncthreads();

    // gather A: cols [0,64) = h[row[e]], [64,128) = ea[e]
    #pragma unroll
    for (int i = 0; i < 8; ++i) {
        int f = tid + i * 512; int e = f >> 5, p = f & 31;
        float4 v;
        if (p < 16) v = *(const float4*)(g_hcur + (size_t)sRow[e] * 64 + p * 4);
        else        v = *(const float4*)(ea_in + (size_t)(e0 + e) * 64 + (p - 16) * 4);
        *(float4*)&sA[e * 132 + p * 4] = v;
    }
    __syncthreads();

    const int wid = tid >> 5, lane = tid & 31;
    const int g = lane >> 2, t = lane & 3;

    float acc[2][8][4];
    #pragma unroll
    for (int mi = 0; mi < 2; ++mi)
        #pragma unroll
        for (int ni = 0; ni < 8; ++ni)
            #pragma unroll
            for (int q = 0; q < 4; ++q) acc[mi][ni][q] = 0.f;

    // ---- GEMM1: hid[128][128] = A @ W1 (warps 0-7, 32x64 tiles)
    if (wid < 8) {
        const int r0 = (wid & 3) * 32, n0 = (wid >> 2) * 64;
        #pragma unroll
        for (int k0 = 0; k0 < 128; k0 += 8) {
            uint32_t ahi[2][4], alo[2][4];
            #pragma unroll
            for (int mi = 0; mi < 2; ++mi) {
                const float* ap = sA + (r0 + 16 * mi + g) * 132 + k0 + t;
                split_tf(ap[0],           ahi[mi][0], alo[mi][0]);
                split_tf(ap[8 * 132],     ahi[mi][1], alo[mi][1]);
                split_tf(ap[4],           ahi[mi][2], alo[mi][2]);
                split_tf(ap[8 * 132 + 4], ahi[mi][3], alo[mi][3]);
            }
            #pragma unroll
            for (int ni = 0; ni < 8; ++ni) {
                const float* bp = sW1 + (k0 + t) * 132 + n0 + 8 * ni + g;
                uint32_t bh0, bl0, bh1, bl1;
                split_tf(bp[0],       bh0, bl0);
                split_tf(bp[4 * 132], bh1, bl1);
                mma_tf32(acc[0][ni], ahi[0], bh0, bh1);
                mma_tf32(acc[0][ni], ahi[0], bl0, bl1);
                mma_tf32(acc[0][ni], alo[0], bh0, bh1);
                mma_tf32(acc[1][ni], ahi[1], bh0, bh1);
                mma_tf32(acc[1][ni], ahi[1], bl0, bl1);
                mma_tf32(acc[1][ni], alo[1], bh0, bh1);
            }
        }
    }
    __syncthreads();   // everyone done reading A
    if (wid < 8) {     // bias + ReLU, write hid in place
        const int r0 = (wid & 3) * 32, n0 = (wid >> 2) * 64;
        #pragma unroll
        for (int mi = 0; mi < 2; ++mi) {
            #pragma unroll
            for (int ni = 0; ni < 8; ++ni) {
                int row = r0 + 16 * mi + g, cc = n0 + 8 * ni + 2 * t;
                float bb0 = sB1[cc], bb1 = sB1[cc + 1];
                float2 lo = {fmaxf(acc[mi][ni][0] + bb0, 0.f),
                             fmaxf(acc[mi][ni][1] + bb1, 0.f)};
                float2 hi = {fmaxf(acc[mi][ni][2] + bb0, 0.f),
                             fmaxf(acc[mi][ni][3] + bb1, 0.f)};
                *(float2*)&sA[row * 132 + cc] = lo;
                *(float2*)&sA[(row + 8) * 132 + cc] = hi;
            }
        }
    }
    __syncthreads();

    // ---- GEMM2: out[128][64] = hid @ W2 (warps 0-3, 32x64 tiles)
    if (wid < 4) {
        const int r0 = wid * 32;
        #pragma unroll
        for (int mi = 0; mi < 2; ++mi)
            #pragma unroll
            for (int ni = 0; ni < 8; ++ni)
                #pragma unroll
                for (int q = 0; q < 4; ++q) acc[mi][ni][q] = 0.f;
        #pragma unroll
        for (int k0 = 0; k0 < 128; k0 += 8) {
            uint32_t ahi[2][4], alo[2][4];
            #pragma unroll
            for (int mi = 0; mi < 2; ++mi) {
                const float* ap = sA + (r0 + 16 * mi + g) * 132 + k0 + t;
                split_tf(ap[0],           ahi[mi][0], alo[mi][0]);
                split_tf(ap[8 * 132],     ahi[mi][1], alo[mi][1]);
                split_tf(ap[4],           ahi[mi][2], alo[mi][2]);
                split_tf(ap[8 * 132 + 4], ahi[mi][3], alo[mi][3]);
            }
            #pragma unroll
            for (int ni = 0; ni < 8; ++ni) {
                const float* bp = sW2 + (k0 + t) * 68 + 8 * ni + g;
                uint32_t bh0, bl0, bh1, bl1;
                split_tf(bp[0],      bh0, bl0);
                split_tf(bp[4 * 68], bh1, bl1);
                mma_tf32(acc[0][ni], ahi[0], bh0, bh1);
                mma_tf32(acc[0][ni], ahi[0], bl0, bl1);
                mma_tf32(acc[0][ni], alo[0], bh0, bh1);
                mma_tf32(acc[1][ni], ahi[1], bh0, bh1);
                mma_tf32(acc[1][ni], ahi[1], bl0, bl1);
                mma_tf32(acc[1][ni], alo[1], bh0, bh1);
            }
        }
        // epilogue: +b2, store ea, scatter node sums, SMEM graph pool
        int gmin = sGB[0];
        #pragma unroll
        for (int mi = 0; mi < 2; ++mi) {
            int el0 = r0 + 16 * mi + g, el1 = el0 + 8;
            int col0 = sCol[el0], col1 = sCol[el1];
            int gb0 = sGB[el0], gb1 = sGB[el1];
            int s0 = gb0 - gmin, s1 = gb1 - gmin;
            #pragma unroll
            for (int ni = 0; ni < 8; ++ni) {
                int cc = 8 * ni + 2 * t;
                float bb0 = sB2[cc], bb1 = sB2[cc + 1];
                float2 lo = {acc[mi][ni][0] + bb0, acc[mi][ni][1] + bb1};
                float2 hi = {acc[mi][ni][2] + bb0, acc[mi][ni][3] + bb1};
                *(float2*)(g_ea + (size_t)(e0 + el0) * 64 + cc) = lo;
                *(float2*)(g_ea + (size_t)(e0 + el1) * 64 + cc) = hi;
                red2(&g_hsum[(size_t)col0 * 64 + cc], lo);
                red2(&g_hsum[(size_t)col1 * 64 + cc], hi);
                if (s0 < 2) {
                    atomicAdd(&sGE[s0 * 64 + cc], lo.x);
                    atomicAdd(&sGE[s0 * 64 + cc + 1], lo.y);
                } else red2(&geout[gb0 * 64 + cc], lo);
                if (s1 < 2) {
                    atomicAdd(&sGE[s1 * 64 + cc], hi.x);
                    atomicAdd(&sGE[s1 * 64 + cc + 1], hi.y);
                } else red2(&geout[gb1 * 64 + cc], hi);
            }
        }
    }
    __syncthreads();
    if (tid < 128) {     // flush SMEM graph pool
        int sl = tid >> 6, cc = tid & 63;
        int gg = sGB[0] + sl;
        if (gg < NGR) {
            float pv = sGE[tid];
            if (pv != 0.f) red1(&geout[gg * 64 + cc], pv);
        }
    }
}

// ---------------- output head: one block per graph ----------------------------
__global__ void k_head(const float* __restrict__ Wo1, const float* __restrict__ bo1,
                       const float* __restrict__ Wo2, const float* __restrict__ bo2,
                       const float* __restrict__ Wo3, const float* __restrict__ bo3,
                       float* __restrict__ out) {
    __shared__ float aa[512];
    __shared__ float s1[128];
    __shared__ float s2[128];
    int g = blockIdx.x;
    int tid = threadIdx.x;
    float ninv = 1.f / fmaxf((float)g_cnt_ng[g], 1.f);
    float einv = 1.f / fmaxf((float)g_cnt_eg[g], 1.f);
    for (int i = tid; i < 512; i += 128) {
        float v;
        if (i < 256) {
            v = g_gnsum[(i >> 6) * NGR * 64 + g * 64 + (i & 63)] * ninv;
            out[g * 256 + i] = v;
        } else {
            int c = i - 256;
            v = g_gesum[(c >> 6) * NGR * 64 + g * 64 + (c & 63)] * einv;
            out[4096 + g * 256 + c] = v;
        }
        aa[i] = v;
    }
    __syncthreads();
    {
        float s = bo1[tid];
        for (int k = 0; k < 512; ++k) s = fmaf(aa[k], Wo1[k * 128 + tid], s);
        s1[tid] = fmaxf(s, 0.f);
    }
    __syncthreads();
    {
        float s = bo2[tid];
        for (int k = 0; k < 128; ++k) s = fmaf(s1[k], Wo2[k * 128 + tid], s);
        s2[tid] = fmaxf(s, 0.f);
    }
    __syncthreads();
    if (tid < 32) {
        float s = bo3[tid];
        for (int k = 0; k < 128; ++k) s = fmaf(s2[k], Wo3[k * 32 + tid], s);
        out[8192 + g * 32 + tid] = s;
    }
}

// ---------------- launcher ----------------------------------------------------
extern "C" void kernel_launch(void* const* d_in, const int* in_sizes, int n_in,
                              void* d_out, int out_size) {
    const float* edge_attr = (const float*)d_in[1];
    const int*   eidx      = (const int*)d_in[3];
    const int*   batch     = (const int*)d_in[4];
    const int*   eb        = (const int*)d_in[5];
    const float* W1s       = (const float*)d_in[6];
    const float* b1s       = (const float*)d_in[7];
    const float* W2s       = (const float*)d_in[8];
    const float* b2s       = (const float*)d_in[9];
    const float* Wo1       = (const float*)d_in[10];
    const float* bo1       = (const float*)d_in[11];
    const float* Wo2       = (const float*)d_in[12];
    const float* bo2       = (const float*)d_in[13];
    const float* Wo3       = (const float*)d_in[14];
    const float* bo3       = (const float*)d_in[15];
    float* out = (float*)d_out;

    cudaFuncSetAttribute((const void*)k_mlp,
                         cudaFuncAttributeMaxDynamicSharedMemorySize,
                         SMEM_MLP_BYTES);

    k_init<<<2048, 256>>>();
    k_node_cnt<<<(N_CNT + 255) / 256, 256>>>(batch);
    k_pool0<<<E_CNT / 16, 256>>>(edge_attr, eidx, eb);
    k_finalize<<<N_CNT / 16, 256>>>(0, batch);

    for (int l = 0; l < NLAY; ++l) {
        k_mlp<<<E_CNT / TE, 512, SMEM_MLP_BYTES>>>(
            edge_attr, eidx, eb,
            W1s + l * 128 * 128, b1s + l * 128,
            W2s + l * 128 * 64, b2s + l * 64, l);
        k_finalize<<<N_CNT / 16, 256>>>(l + 1, batch);
    }

    k_head<<<NGR, 128>>>(Wo1, bo1, Wo2, bo2, Wo3, bo3, out);
}

// round 4
// speedup vs baseline: 3.4537x; 2.4687x over previous
#include <cuda_runtime.h>
#include <cuda_bf16.h>
#include <cstdint>

// Problem constants (fixed by the dataset)
#define E_CNT   800000
#define N_CNT   50000
#define NGR     16
#define NLAY    3
#define TE      128      // edges per k_mlp block

// ---------------- scratch (device globals; no allocations allowed) ----------
__device__ float g_ea[E_CNT * 64];            // edge features (per-layer output)
__device__ float g_hcur[N_CNT * 64];          // node features h
__device__ float g_hsum[N_CNT * 64];          // scatter-sum accumulator
__device__ int   g_cnt_node[N_CNT];           // in-degree per node
__device__ int   g_cnt_ng[NGR];               // nodes per graph
__device__ int   g_cnt_eg[NGR];               // edges per graph
__device__ float g_gnsum[(NLAY + 1) * NGR * 64];  // node pools (sums)
__device__ float g_gesum[(NLAY + 1) * NGR * 64];  // edge pools (sums)
// pre-split transposed weights: packed words {hi(bf16x2), lo(bf16x2)} per 2 k
__device__ uint2 g_W1t[NLAY * 128 * 64];      // [l][n(128)][kpair(64)]
__device__ uint2 g_W2t[NLAY * 64 * 64];       // [l][n(64)][kpair(64)]

// ---------------- PTX helpers ------------------------------------------------
__device__ __forceinline__ void red4(float* p, float4 v) {
    asm volatile("red.global.add.v4.f32 [%0], {%1,%2,%3,%4};"
                 :: "l"(p), "f"(v.x), "f"(v.y), "f"(v.z), "f"(v.w) : "memory");
}
__device__ __forceinline__ void red2(float* p, float2 v) {
    asm volatile("red.global.add.v2.f32 [%0], {%1,%2};"
                 :: "l"(p), "f"(v.x), "f"(v.y) : "memory");
}
__device__ __forceinline__ void red1(float* p, float v) {
    asm volatile("red.global.add.f32 [%0], %1;" :: "l"(p), "f"(v) : "memory");
}
// split two consecutive-k f32 values into packed bf16x2 {hi word, lo word}
__device__ __forceinline__ uint2 splitpack2(float a, float b) {
    __nv_bfloat16 ha = __float2bfloat16_rn(a);
    __nv_bfloat16 hb = __float2bfloat16_rn(b);
    __nv_bfloat16 la = __float2bfloat16_rn(a - __bfloat162float(ha));
    __nv_bfloat16 lb = __float2bfloat16_rn(b - __bfloat162float(hb));
    __nv_bfloat162 hv = __halves2bfloat162(ha, hb);   // .x = even k (low)
    __nv_bfloat162 lv = __halves2bfloat162(la, lb);
    uint2 r;
    r.x = *reinterpret_cast<uint32_t*>(&hv);
    r.y = *reinterpret_cast<uint32_t*>(&lv);
    return r;
}
// m16n8k16 bf16 mma, row.col, f32 accumulate. Fragment map (PTX ISA):
//  A regs (bf16x2): a0=(row g, k 2t..2t+1) a1=(g+8, same) a2=(g, 8+2t..) a3=(g+8, 8+2t..)
//  B regs: b0=(k 2t..2t+1, col g) b1=(k 8+2t.., col g)
//  C: c0=(g,2t) c1=(g,2t+1) c2=(g+8,2t) c3=(g+8,2t+1)
__device__ __forceinline__ void mma_bf16(float* d, uint32_t a0, uint32_t a1,
                                         uint32_t a2, uint32_t a3,
                                         uint32_t b0, uint32_t b1) {
    asm volatile(
        "mma.sync.aligned.m16n8k16.row.col.f32.bf16.bf16.f32 "
        "{%0,%1,%2,%3}, {%4,%5,%6,%7}, {%8,%9}, {%0,%1,%2,%3};"
        : "+f"(d[0]), "+f"(d[1]), "+f"(d[2]), "+f"(d[3])
        : "r"(a0), "r"(a1), "r"(a2), "r"(a3), "r"(b0), "r"(b1));
}

// ---------------- init: zero accumulators ------------------------------------
__global__ void k_init() {
    int t = blockIdx.x * blockDim.x + threadIdx.x;
    int stride = gridDim.x * blockDim.x;
    for (int i = t; i < N_CNT * 64; i += stride) g_hsum[i] = 0.f;
    for (int i = t; i < N_CNT; i += stride) g_cnt_node[i] = 0;
    for (int i = t; i < (NLAY + 1) * NGR * 64; i += stride) {
        g_gnsum[i] = 0.f;
        g_gesum[i] = 0.f;
    }
    for (int i = t; i < NGR; i += stride) { g_cnt_ng[i] = 0; g_cnt_eg[i] = 0; }
}

// ---------------- weight prep: transpose + bf16 hi/lo split (once) -----------
__global__ void k_wprep(const float* __restrict__ W1s, const float* __restrict__ W2s) {
    int t = blockIdx.x * blockDim.x + threadIdx.x;
    if (t < NLAY * 128 * 64) {                 // W1t: l, n(128), kp(64)
        int kp = t & 63, n = (t >> 6) & 127, l = t >> 13;
        float v0 = W1s[l * 16384 + (2 * kp) * 128 + n];
        float v1 = W1s[l * 16384 + (2 * kp + 1) * 128 + n];
        g_W1t[t] = splitpack2(v0, v1);
    } else {
        int u = t - NLAY * 128 * 64;
        if (u < NLAY * 64 * 64) {              // W2t: l, n(64), kp(64)
            int kp = u & 63, n = (u >> 6) & 63, l = u >> 12;
            float v0 = W2s[l * 8192 + (2 * kp) * 64 + n];
            float v1 = W2s[l * 8192 + (2 * kp + 1) * 64 + n];
            g_W2t[u] = splitpack2(v0, v1);
        }
    }
}

// ---------------- nodes-per-graph counts --------------------------------------
__global__ void k_node_cnt(const int* __restrict__ batch) {
    int t = blockIdx.x * blockDim.x + threadIdx.x;
    if (t < N_CNT) atomicAdd(&g_cnt_ng[batch[t]], 1);
}

// ---------------- layer-0 pooling + degree counts ------------------------------
__global__ void k_pool0(const float* __restrict__ edge_attr,
                        const int* __restrict__ eidx,
                        const int* __restrict__ eb) {
    __shared__ float sP[128];
    __shared__ int sCnt[2];
    __shared__ int s_gmin;
    int tid = threadIdx.x;
    int e = blockIdx.x * 16 + (tid >> 4);
    int c4 = tid & 15;
    if (tid < 128) sP[tid] = 0.f;
    if (tid < 2) sCnt[tid] = 0;
    if (tid == 0) s_gmin = eb[blockIdx.x * 16];
    __syncthreads();

    float4 v = *(const float4*)(edge_attr + (size_t)e * 64 + c4 * 4);
    int c = eidx[E_CNT + e];
    int g = eb[e];
    red4(&g_hsum[(size_t)c * 64 + c4 * 4], v);
    if (c4 == 0) atomicAdd(&g_cnt_node[c], 1);

    int slot = g - s_gmin;
    if (slot < 2) {
        atomicAdd(&sP[slot * 64 + c4 * 4 + 0], v.x);
        atomicAdd(&sP[slot * 64 + c4 * 4 + 1], v.y);
        atomicAdd(&sP[slot * 64 + c4 * 4 + 2], v.z);
        atomicAdd(&sP[slot * 64 + c4 * 4 + 3], v.w);
        if (c4 == 0) atomicAdd(&sCnt[slot], 1);
    } else {
        red4(&g_gesum[g * 64 + c4 * 4], v);
        if (c4 == 0) atomicAdd(&g_cnt_eg[g], 1);
    }
    __syncthreads();
    if (tid < 32) {
        int sl = tid >> 4, cc = (tid & 15) * 4;
        int gg = s_gmin + sl;
        if (gg < NGR) {
            float4 p = *(float4*)&sP[sl * 64 + cc];
            if (p.x != 0.f || p.y != 0.f || p.z != 0.f || p.w != 0.f)
                red4(&g_gesum[gg * 64 + cc], p);
            if ((tid & 15) == 0 && sCnt[sl] > 0) atomicAdd(&g_cnt_eg[gg], sCnt[sl]);
        }
    }
}

// ---------------- finalize h = h_sum/max(deg,1); pool to gn; zero h_sum --------
__global__ void k_finalize(int li, const int* __restrict__ batch) {
    __shared__ float sP[128];
    __shared__ int s_gmin;
    int tid = threadIdx.x;
    int v = blockIdx.x * 16 + (tid >> 4);
    int c4 = tid & 15;
    if (tid < 128) sP[tid] = 0.f;
    if (tid == 0) s_gmin = batch[blockIdx.x * 16];
    __syncthreads();

    float4 s = *(float4*)(g_hsum + (size_t)v * 64 + c4 * 4);
    float inv = 1.f / fmaxf((float)g_cnt_node[v], 1.f);
    float4 h = {s.x * inv, s.y * inv, s.z * inv, s.w * inv};
    *(float4*)(g_hcur + (size_t)v * 64 + c4 * 4) = h;
    float4 z = {0.f, 0.f, 0.f, 0.f};
    *(float4*)(g_hsum + (size_t)v * 64 + c4 * 4) = z;

    int gb = batch[v];
    int slot = gb - s_gmin;
    if (slot < 2) {
        atomicAdd(&sP[slot * 64 + c4 * 4 + 0], h.x);
        atomicAdd(&sP[slot * 64 + c4 * 4 + 1], h.y);
        atomicAdd(&sP[slot * 64 + c4 * 4 + 2], h.z);
        atomicAdd(&sP[slot * 64 + c4 * 4 + 3], h.w);
    } else {
        red4(&g_gnsum[li * NGR * 64 + gb * 64 + c4 * 4], h);
    }
    __syncthreads();
    if (tid < 32) {
        int sl = tid >> 4, cc = (tid & 15) * 4;
        int gg = s_gmin + sl;
        if (gg < NGR) {
            float4 p = *(float4*)&sP[sl * 64 + cc];
            if (p.x != 0.f || p.y != 0.f || p.z != 0.f || p.w != 0.f)
                red4(&g_gnsum[li * NGR * 64 + gg * 64 + cc], p);
        }
    }
}

// ---------------- fused edge MLP (bf16x3 tensor cores) + scatter ---------------
// Block: 128 edges, 512 threads (16 warps). All operands pre-split bf16 {hi,lo}
// packed as uint2 words of 2 consecutive k. SMEM word-row stride 68 uint2
// (conflict-free fragment loads). Inner loops: pure LDS.64 + MMA.
// GEMM1: 16 warps x 32x32 tiles. GEMM2: 16 warps x 32x16 tiles.
#define LDA 68
#define SMEM_MLP_BYTES ((128*LDA + 128*LDA + 64*LDA) * 8 + (128 + 64 + 128) * 4 + 384 * 4)

__global__ void __launch_bounds__(512, 1)
k_mlp(const float* __restrict__ edge_attr,
      const int* __restrict__ eidx, const int* __restrict__ eb,
      const float* __restrict__ b1, const float* __restrict__ b2,
      int layer) {
    extern __shared__ uint2 smu[];
    uint2* sA  = smu;                    // [128][68] activations / hid (in place)
    uint2* sW1 = sA + 128 * LDA;         // [128][68]
    uint2* sW2 = sW1 + 128 * LDA;        // [64][68]
    float* sB1 = (float*)(sW2 + 64 * LDA);
    float* sB2 = sB1 + 128;
    float* sGE = sB2 + 64;               // [2][64] graph-pool accum
    int* sRow = (int*)(sGE + 128);
    int* sCol = sRow + 128;
    int* sGB  = sCol + 128;

    const float* ea_in = (layer == 0) ? edge_attr : g_ea;
    float* geout = g_gesum + (layer + 1) * NGR * 64;
    const uint2* pw1 = g_W1t + layer * 128 * 64;
    const uint2* pw2 = g_W2t + layer * 64 * 64;

    const int tid = threadIdx.x;
    const int e0 = blockIdx.x * TE;

    if (tid < 128) { sRow[tid] = eidx[e0 + tid]; sB1[tid] = b1[tid]; sGE[tid] = 0.f; }
    else if (tid < 256) { sCol[tid - 128] = eidx[E_CNT + e0 + tid - 128]; }
    else if (tid < 384) { sGB[tid - 256] = eb[e0 + tid - 256]; }
    else if (tid < 448) { sB2[tid - 384] = b2[tid - 384]; }

    #pragma unroll
    for (int i = 0; i < 16; ++i) {       // W1t copy: 8192 uint2
        int f = tid + i * 512; int r = f >> 6, w = f & 63;
        sW1[r * LDA + w] = pw1[f];
    }
    #pragma unroll
    for (int i = 0; i < 8; ++i) {        // W2t copy: 4096 uint2
        int f = tid + i * 512; int r = f >> 6, w = f & 63;
        sW2[r * LDA + w] = pw2[f];
    }
    __syncthreads();

    // gather A + split: cols [0,64) = h[row[e]], [64,128) = ea[e]
    #pragma unroll
    for (int i = 0; i < 8; ++i) {
        int f = tid + i * 512; int e = f >> 5, p = f & 31;
        float4 v;
        if (p < 16) v = *(const float4*)(g_hcur + (size_t)sRow[e] * 64 + p * 4);
        else        v = *(const float4*)(ea_in + (size_t)(e0 + e) * 64 + (p - 16) * 4);
        uint2 w0 = splitpack2(v.x, v.y);
        uint2 w1 = splitpack2(v.z, v.w);
        uint4 pk = {w0.x, w0.y, w1.x, w1.y};
        *(uint4*)&sA[e * LDA + p * 2] = pk;   // two consecutive uint2 words
    }
    __syncthreads();

    const int wid = tid >> 5, lane = tid & 31;
    const int g = lane >> 2, t = lane & 3;
    const int r0 = (wid & 3) * 32;

    // ---- GEMM1: hid[128][128] = A @ W1 ; warp tile 32x32
    const int n0 = (wid >> 2) * 32;
    float acc[2][4][4];
    #pragma unroll
    for (int mi = 0; mi < 2; ++mi)
        #pragma unroll
        for (int ni = 0; ni < 4; ++ni)
            #pragma unroll
            for (int q = 0; q < 4; ++q) acc[mi][ni][q] = 0.f;

    #pragma unroll
    for (int ks = 0; ks < 8; ++ks) {
        const int kw = ks * 8;
        uint32_t ahi[2][4], alo[2][4];
        #pragma unroll
        for (int mi = 0; mi < 2; ++mi) {
            const uint2* ap = sA + (r0 + 16 * mi + g) * LDA + kw + t;
            uint2 A0 = ap[0], A1 = ap[8 * LDA], A2 = ap[4], A3 = ap[8 * LDA + 4];
            ahi[mi][0] = A0.x; ahi[mi][1] = A1.x; ahi[mi][2] = A2.x; ahi[mi][3] = A3.x;
            alo[mi][0] = A0.y; alo[mi][1] = A1.y; alo[mi][2] = A2.y; alo[mi][3] = A3.y;
        }
        #pragma unroll
        for (int ni = 0; ni < 4; ++ni) {
            const uint2* bp = sW1 + (n0 + 8 * ni + g) * LDA + kw + t;
            uint2 B0 = bp[0], B1 = bp[4];
            #pragma unroll
            for (int mi = 0; mi < 2; ++mi) {
                mma_bf16(acc[mi][ni], ahi[mi][0], ahi[mi][1], ahi[mi][2], ahi[mi][3], B0.x, B1.x);
                mma_bf16(acc[mi][ni], ahi[mi][0], ahi[mi][1], ahi[mi][2], ahi[mi][3], B0.y, B1.y);
                mma_bf16(acc[mi][ni], alo[mi][0], alo[mi][1], alo[mi][2], alo[mi][3], B0.x, B1.x);
            }
        }
    }
    __syncthreads();   // all warps done reading A

    // bias + ReLU, split hid, write back in place
    #pragma unroll
    for (int mi = 0; mi < 2; ++mi) {
        int row = r0 + 16 * mi + g;
        #pragma unroll
        for (int ni = 0; ni < 4; ++ni) {
            int cc = n0 + 8 * ni + 2 * t;
            float bb0 = sB1[cc], bb1 = sB1[cc + 1];
            float v0 = fmaxf(acc[mi][ni][0] + bb0, 0.f);
            float v1 = fmaxf(acc[mi][ni][1] + bb1, 0.f);
            float v2 = fmaxf(acc[mi][ni][2] + bb0, 0.f);
            float v3 = fmaxf(acc[mi][ni][3] + bb1, 0.f);
            int wd = (n0 >> 1) + 4 * ni + t;
            sA[row * LDA + wd] = splitpack2(v0, v1);
            sA[(row + 8) * LDA + wd] = splitpack2(v2, v3);
        }
    }
    __syncthreads();

    // ---- GEMM2: out[128][64] = hid @ W2 ; warp tile 32x16
    const int n20 = (wid >> 2) * 16;
    float acc2[2][2][4];
    #pragma unroll
    for (int mi = 0; mi < 2; ++mi)
        #pragma unroll
        for (int ni = 0; ni < 2; ++ni)
            #pragma unroll
            for (int q = 0; q < 4; ++q) acc2[mi][ni][q] = 0.f;

    #pragma unroll
    for (int ks = 0; ks < 8; ++ks) {
        const int kw = ks * 8;
        uint32_t ahi[2][4], alo[2][4];
        #pragma unroll
        for (int mi = 0; mi < 2; ++mi) {
            const uint2* ap = sA + (r0 + 16 * mi + g) * LDA + kw + t;
            uint2 A0 = ap[0], A1 = ap[8 * LDA], A2 = ap[4], A3 = ap[8 * LDA + 4];
            ahi[mi][0] = A0.x; ahi[mi][1] = A1.x; ahi[mi][2] = A2.x; ahi[mi][3] = A3.x;
            alo[mi][0] = A0.y; alo[mi][1] = A1.y; alo[mi][2] = A2.y; alo[mi][3] = A3.y;
        }
        #pragma unroll
        for (int ni = 0; ni < 2; ++ni) {
            const uint2* bp = sW2 + (n20 + 8 * ni + g) * LDA + kw + t;
            uint2 B0 = bp[0], B1 = bp[4];
            #pragma unroll
            for (int mi = 0; mi < 2; ++mi) {
                mma_bf16(acc2[mi][ni], ahi[mi][0], ahi[mi][1], ahi[mi][2], ahi[mi][3], B0.x, B1.x);
                mma_bf16(acc2[mi][ni], ahi[mi][0], ahi[mi][1], ahi[mi][2], ahi[mi][3], B0.y, B1.y);
                mma_bf16(acc2[mi][ni], alo[mi][0], alo[mi][1], alo[mi][2], alo[mi][3], B0.x, B1.x);
            }
        }
    }

    // epilogue: +b2, store ea, scatter node sums, SMEM graph pool
    int gmin = sGB[0];
    #pragma unroll
    for (int mi = 0; mi < 2; ++mi) {
        int el0 = r0 + 16 * mi + g, el1 = el0 + 8;
        int col0 = sCol[el0], col1 = sCol[el1];
        int gb0 = sGB[el0], gb1 = sGB[el1];
        int s0 = gb0 - gmin, s1 = gb1 - gmin;
        #pragma unroll
        for (int ni = 0; ni < 2; ++ni) {
            int cc = n20 + 8 * ni + 2 * t;
            float bb0 = sB2[cc], bb1 = sB2[cc + 1];
            float2 lo = {acc2[mi][ni][0] + bb0, acc2[mi][ni][1] + bb1};
            float2 hi = {acc2[mi][ni][2] + bb0, acc2[mi][ni][3] + bb1};
            *(float2*)(g_ea + (size_t)(e0 + el0) * 64 + cc) = lo;
            *(float2*)(g_ea + (size_t)(e0 + el1) * 64 + cc) = hi;
            red2(&g_hsum[(size_t)col0 * 64 + cc], lo);
            red2(&g_hsum[(size_t)col1 * 64 + cc], hi);
            if (s0 < 2) {
                atomicAdd(&sGE[s0 * 64 + cc], lo.x);
                atomicAdd(&sGE[s0 * 64 + cc + 1], lo.y);
            } else red2(&geout[gb0 * 64 + cc], lo);
            if (s1 < 2) {
                atomicAdd(&sGE[s1 * 64 + cc], hi.x);
                atomicAdd(&sGE[s1 * 64 + cc + 1], hi.y);
            } else red2(&geout[gb1 * 64 + cc], hi);
        }
    }
    __syncthreads();
    if (tid < 128) {     // flush SMEM graph pool
        int sl = tid >> 6, cc = tid & 63;
        int gg = sGB[0] + sl;
        if (gg < NGR) {
            float pv = sGE[tid];
            if (pv != 0.f) red1(&geout[gg * 64 + cc], pv);
        }
    }
}

// ---------------- output head: one block per graph ----------------------------
__global__ void k_head(const float* __restrict__ Wo1, const float* __restrict__ bo1,
                       const float* __restrict__ Wo2, const float* __restrict__ bo2,
                       const float* __restrict__ Wo3, const float* __restrict__ bo3,
                       float* __restrict__ out) {
    __shared__ float aa[512];
    __shared__ float s1[128];
    __shared__ float s2[128];
    int g = blockIdx.x;
    int tid = threadIdx.x;
    float ninv = 1.f / fmaxf((float)g_cnt_ng[g], 1.f);
    float einv = 1.f / fmaxf((float)g_cnt_eg[g], 1.f);
    for (int i = tid; i < 512; i += 128) {
        float v;
        if (i < 256) {
            v = g_gnsum[(i >> 6) * NGR * 64 + g * 64 + (i & 63)] * ninv;
            out[g * 256 + i] = v;
        } else {
            int c = i - 256;
            v = g_gesum[(c >> 6) * NGR * 64 + g * 64 + (c & 63)] * einv;
            out[4096 + g * 256 + c] = v;
        }
        aa[i] = v;
    }
    __syncthreads();
    {
        float s = bo1[tid];
        for (int k = 0; k < 512; ++k) s = fmaf(aa[k], Wo1[k * 128 + tid], s);
        s1[tid] = fmaxf(s, 0.f);
    }
    __syncthreads();
    {
        float s = bo2[tid];
        for (int k = 0; k < 128; ++k) s = fmaf(s1[k], Wo2[k * 128 + tid], s);
        s2[tid] = fmaxf(s, 0.f);
    }
    __syncthreads();
    if (tid < 32) {
        float s = bo3[tid];
        for (int k = 0; k < 128; ++k) s = fmaf(s2[k], Wo3[k * 32 + tid], s);
        out[8192 + g * 32 + tid] = s;
    }
}

// ---------------- launcher ----------------------------------------------------
extern "C" void kernel_launch(void* const* d_in, const int* in_sizes, int n_in,
                              void* d_out, int out_size) {
    const float* edge_attr = (const float*)d_in[1];
    const int*   eidx      = (const int*)d_in[3];
    const int*   batch     = (const int*)d_in[4];
    const int*   eb        = (const int*)d_in[5];
    const float* W1s       = (const float*)d_in[6];
    const float* b1s       = (const float*)d_in[7];
    const float* W2s       = (const float*)d_in[8];
    const float* b2s       = (const float*)d_in[9];
    const float* Wo1       = (const float*)d_in[10];
    const float* bo1       = (const float*)d_in[11];
    const float* Wo2       = (const float*)d_in[12];
    const float* bo2       = (const float*)d_in[13];
    const float* Wo3       = (const float*)d_in[14];
    const float* bo3       = (const float*)d_in[15];
    float* out = (float*)d_out;

    cudaFuncSetAttribute((const void*)k_mlp,
                         cudaFuncAttributeMaxDynamicSharedMemorySize,
                         SMEM_MLP_BYTES);

    k_init<<<2048, 256>>>();
    k_wprep<<<(NLAY * 128 * 64 + NLAY * 64 * 64 + 255) / 256, 256>>>(W1s, W2s);
    k_node_cnt<<<(N_CNT + 255) / 256, 256>>>(batch);
    k_pool0<<<E_CNT / 16, 256>>>(edge_attr, eidx, eb);
    k_finalize<<<N_CNT / 16, 256>>>(0, batch);

    for (int l = 0; l < NLAY; ++l) {
        k_mlp<<<E_CNT / TE, 512, SMEM_MLP_BYTES>>>(
            edge_attr, eidx, eb, b1s + l * 128, b2s + l * 64, l);
        k_finalize<<<N_CNT / 16, 256>>>(l + 1, batch);
    }

    k_head<<<NGR, 128>>>(Wo1, bo1, Wo2, bo2, Wo3, bo3, out);
}

// round 6
// speedup vs baseline: 8.1559x; 2.3615x over previous
#include <cuda_runtime.h>
#include <cuda_bf16.h>
#include <cstdint>

// Problem constants (fixed by the dataset)
#define E_CNT   800000
#define N_CNT   50000
#define NGR     16
#define NLAY    3
#define TE      128      // edges per k_mlp block

// ---------------- scratch (device globals; no allocations allowed) ----------
__device__ float g_ea[E_CNT * 64];            // edge features (per-layer output)
__device__ float g_hcur[N_CNT * 64];          // node features h
__device__ float g_hw[N_CNT * 128];           // hW = h @ W1top + b1 (per layer)
__device__ float g_hsum[N_CNT * 64];          // scatter-sum accumulator
__device__ int   g_cnt_node[N_CNT];           // in-degree per node
__device__ int   g_cnt_ng[NGR];               // nodes per graph
__device__ int   g_cnt_eg[NGR];               // edges per graph
__device__ float g_gnsum[(NLAY + 1) * NGR * 64];  // node pools (sums)
__device__ float g_gesum[(NLAY + 1) * NGR * 64];  // edge pools (sums)
// pre-split transposed weights: packed words {hi(bf16x2), lo(bf16x2)} per 2 k
__device__ uint2 g_W1t[NLAY * 128 * 64];      // [l][n(128)][kpair(64)]
__device__ uint2 g_W2t[NLAY * 64 * 64];       // [l][n(64)][kpair(64)]

// ---------------- PTX helpers ------------------------------------------------
__device__ __forceinline__ void red4(float* p, float4 v) {
    asm volatile("red.global.add.v4.f32 [%0], {%1,%2,%3,%4};"
                 :: "l"(p), "f"(v.x), "f"(v.y), "f"(v.z), "f"(v.w) : "memory");
}
__device__ __forceinline__ void red2(float* p, float2 v) {
    asm volatile("red.global.add.v2.f32 [%0], {%1,%2};"
                 :: "l"(p), "f"(v.x), "f"(v.y) : "memory");
}
__device__ __forceinline__ void red1(float* p, float v) {
    asm volatile("red.global.add.f32 [%0], %1;" :: "l"(p), "f"(v) : "memory");
}
// split two consecutive-k f32 values into packed bf16x2 {hi word, lo word}
__device__ __forceinline__ uint2 splitpack2(float a, float b) {
    __nv_bfloat16 ha = __float2bfloat16_rn(a);
    __nv_bfloat16 hb = __float2bfloat16_rn(b);
    __nv_bfloat16 la = __float2bfloat16_rn(a - __bfloat162float(ha));
    __nv_bfloat16 lb = __float2bfloat16_rn(b - __bfloat162float(hb));
    __nv_bfloat162 hv = __halves2bfloat162(ha, hb);   // .x = even k
    __nv_bfloat162 lv = __halves2bfloat162(la, lb);
    uint2 r;
    r.x = *reinterpret_cast<uint32_t*>(&hv);
    r.y = *reinterpret_cast<uint32_t*>(&lv);
    return r;
}
// m16n8k16 bf16 mma, row.col, f32 accumulate (fragment map per PTX ISA)
__device__ __forceinline__ void mma_bf16(float* d, uint32_t a0, uint32_t a1,
                                         uint32_t a2, uint32_t a3,
                                         uint32_t b0, uint32_t b1) {
    asm volatile(
        "mma.sync.aligned.m16n8k16.row.col.f32.bf16.bf16.f32 "
        "{%0,%1,%2,%3}, {%4,%5,%6,%7}, {%8,%9}, {%0,%1,%2,%3};"
        : "+f"(d[0]), "+f"(d[1]), "+f"(d[2]), "+f"(d[3])
        : "r"(a0), "r"(a1), "r"(a2), "r"(a3), "r"(b0), "r"(b1));
}

// ---------------- init: zero accumulators ------------------------------------
__global__ void k_init() {
    int t = blockIdx.x * blockDim.x + threadIdx.x;
    int stride = gridDim.x * blockDim.x;
    for (int i = t; i < N_CNT * 64; i += stride) g_hsum[i] = 0.f;
    for (int i = t; i < N_CNT; i += stride) g_cnt_node[i] = 0;
    for (int i = t; i < (NLAY + 1) * NGR * 64; i += stride) {
        g_gnsum[i] = 0.f;
        g_gesum[i] = 0.f;
    }
    for (int i = t; i < NGR; i += stride) { g_cnt_ng[i] = 0; g_cnt_eg[i] = 0; }
}

// ---------------- weight prep: transpose + bf16 hi/lo split (once) -----------
__global__ void k_wprep(const float* __restrict__ W1s, const float* __restrict__ W2s) {
    int t = blockIdx.x * blockDim.x + threadIdx.x;
    if (t < NLAY * 128 * 64) {                 // W1t: l, n(128), kp(64)
        int kp = t & 63, n = (t >> 6) & 127, l = t >> 13;
        float v0 = W1s[l * 16384 + (2 * kp) * 128 + n];
        float v1 = W1s[l * 16384 + (2 * kp + 1) * 128 + n];
        g_W1t[t] = splitpack2(v0, v1);
    } else {
        int u = t - NLAY * 128 * 64;
        if (u < NLAY * 64 * 64) {              // W2t: l, n(64), kp(64)
            int kp = u & 63, n = (u >> 6) & 63, l = u >> 12;
            float v0 = W2s[l * 8192 + (2 * kp) * 64 + n];
            float v1 = W2s[l * 8192 + (2 * kp + 1) * 64 + n];
            g_W2t[u] = splitpack2(v0, v1);
        }
    }
}

// ---------------- nodes-per-graph counts --------------------------------------
__global__ void k_node_cnt(const int* __restrict__ batch) {
    int t = blockIdx.x * blockDim.x + threadIdx.x;
    if (t < N_CNT) atomicAdd(&g_cnt_ng[batch[t]], 1);
}

// ---------------- layer-0 pooling + degree counts ------------------------------
__global__ void k_pool0(const float* __restrict__ edge_attr,
                        const int* __restrict__ eidx,
                        const int* __restrict__ eb) {
    __shared__ float stg[64 * 68];
    __shared__ float sP[128];
    __shared__ int sGBl[64];
    __shared__ int sColl[64];
    __shared__ int sCnt[2];
    int tid = threadIdx.x;
    int e0 = blockIdx.x * 64;
    if (tid < 128) sP[tid] = 0.f;
    if (tid < 64) { sGBl[tid] = eb[e0 + tid]; sColl[tid] = eidx[E_CNT + e0 + tid]; }
    if (tid < 2) sCnt[tid] = 0;
    __syncthreads();
    int gmin = sGBl[0];

    #pragma unroll
    for (int i = 0; i < 4; ++i) {
        int f = tid + i * 256;                 // 1024 = 64 edges x 16 col4
        int e = f >> 4, c4 = f & 15;
        float4 v = *(const float4*)(edge_attr + (size_t)(e0 + e) * 64 + c4 * 4);
        *(float4*)&stg[e * 68 + c4 * 4] = v;
        red4(&g_hsum[(size_t)sColl[e] * 64 + c4 * 4], v);
        if (c4 == 0) {
            atomicAdd(&g_cnt_node[sColl[e]], 1);
            int sl = sGBl[e] - gmin;
            if (sl < 2) atomicAdd(&sCnt[sl], 1);
            else atomicAdd(&g_cnt_eg[sGBl[e]], 1);
        }
    }
    __syncthreads();
    {
        int q = tid >> 6, c = tid & 63;
        float s0 = 0.f, s1 = 0.f;
        #pragma unroll
        for (int r = q * 16; r < q * 16 + 16; ++r) {
            float val = stg[r * 68 + c];
            int sl = sGBl[r] - gmin;
            if (sl == 0) s0 += val;
            else if (sl == 1) s1 += val;
            else red1(&g_gesum[sGBl[r] * 64 + c], val);
        }
        if (s0 != 0.f) atomicAdd(&sP[c], s0);
        if (s1 != 0.f) atomicAdd(&sP[64 + c], s1);
    }
    __syncthreads();
    if (tid < 128) {
        int sl = tid >> 6, c = tid & 63;
        int gg = gmin + sl;
        if (gg < NGR && sP[tid] != 0.f) red1(&g_gesum[gg * 64 + c], sP[tid]);
        if (tid < 2 && gmin + tid < NGR && sCnt[tid] > 0)
            atomicAdd(&g_cnt_eg[gmin + tid], sCnt[tid]);
    }
}

// ---------------- finalize h = h_sum/max(deg,1); pool to gn; zero h_sum --------
__global__ void k_finalize(int li, const int* __restrict__ batch) {
    __shared__ float sP[128];
    __shared__ int s_gmin;
    int tid = threadIdx.x;
    int v = blockIdx.x * 16 + (tid >> 4);
    int c4 = tid & 15;
    if (tid < 128) sP[tid] = 0.f;
    if (tid == 0) s_gmin = batch[blockIdx.x * 16];
    __syncthreads();

    float4 s = *(float4*)(g_hsum + (size_t)v * 64 + c4 * 4);
    float inv = 1.f / fmaxf((float)g_cnt_node[v], 1.f);
    float4 h = {s.x * inv, s.y * inv, s.z * inv, s.w * inv};
    *(float4*)(g_hcur + (size_t)v * 64 + c4 * 4) = h;
    float4 z = {0.f, 0.f, 0.f, 0.f};
    *(float4*)(g_hsum + (size_t)v * 64 + c4 * 4) = z;

    int gb = batch[v];
    int slot = gb - s_gmin;
    if (slot < 2) {
        atomicAdd(&sP[slot * 64 + c4 * 4 + 0], h.x);
        atomicAdd(&sP[slot * 64 + c4 * 4 + 1], h.y);
        atomicAdd(&sP[slot * 64 + c4 * 4 + 2], h.z);
        atomicAdd(&sP[slot * 64 + c4 * 4 + 3], h.w);
    } else {
        red4(&g_gnsum[li * NGR * 64 + gb * 64 + c4 * 4], h);
    }
    __syncthreads();
    if (tid < 32) {
        int sl = tid >> 4, cc = (tid & 15) * 4;
        int gg = s_gmin + sl;
        if (gg < NGR) {
            float4 p = *(float4*)&sP[sl * 64 + cc];
            if (p.x != 0.f || p.y != 0.f || p.z != 0.f || p.w != 0.f)
                red4(&g_gnsum[li * NGR * 64 + gg * 64 + cc], p);
        }
    }
}

// ---------------- node GEMM: hW = h @ W1top + b1 (per layer) -------------------
// 128 nodes / 256 threads (8 warps). K=64. W1top = W1 rows k<64 (kpairs 0..31).
#define LDH36 36
__global__ void __launch_bounds__(256) k_hw(const float* __restrict__ b1, int layer) {
    __shared__ uint2 sH[128 * LDH36];
    int tid = threadIdx.x;
    int v0 = blockIdx.x * 128;

    #pragma unroll
    for (int i = 0; i < 8; ++i) {              // 2048 float4 = 128 rows x 16
        int f = tid + i * 256;
        int r = f >> 4, c4 = f & 15;
        int node = v0 + r;
        if (node >= N_CNT) node = N_CNT - 1;
        float4 x = *(const float4*)(g_hcur + (size_t)node * 64 + c4 * 4);
        uint2 w0 = splitpack2(x.x, x.y), w1 = splitpack2(x.z, x.w);
        uint4 pk = {w0.x, w0.y, w1.x, w1.y};
        *(uint4*)&sH[r * LDH36 + c4 * 2] = pk;
    }
    __syncthreads();

    const int wid = tid >> 5, lane = tid & 31;
    const int g = lane >> 2, t = lane & 3;
    const int r0 = (wid & 3) * 32, n0 = (wid >> 2) * 64;
    const uint2* pw1 = g_W1t + layer * 128 * 64;

    float acc[2][8][4];
    #pragma unroll
    for (int mi = 0; mi < 2; ++mi)
        #pragma unroll
        for (int ni = 0; ni < 8; ++ni)
            #pragma unroll
            for (int q = 0; q < 4; ++q) acc[mi][ni][q] = 0.f;

    #pragma unroll
    for (int ks = 0; ks < 4; ++ks) {
        int kw = ks * 8;
        uint32_t ahi[2][4], alo[2][4];
        #pragma unroll
        for (int mi = 0; mi < 2; ++mi) {
            const uint2* ap = sH + (r0 + 16 * mi + g) * LDH36 + kw + t;
            uint2 A0 = ap[0], A1 = ap[8 * LDH36], A2 = ap[4], A3 = ap[8 * LDH36 + 4];
            ahi[mi][0] = A0.x; ahi[mi][1] = A1.x; ahi[mi][2] = A2.x; ahi[mi][3] = A3.x;
            alo[mi][0] = A0.y; alo[mi][1] = A1.y; alo[mi][2] = A2.y; alo[mi][3] = A3.y;
        }
        #pragma unroll
        for (int ni = 0; ni < 8; ++ni) {
            const uint2* bp = pw1 + (n0 + 8 * ni + g) * 64 + kw + t;  // kpairs 0..31
            uint2 B0 = bp[0], B1 = bp[4];
            #pragma unroll
            for (int mi = 0; mi < 2; ++mi) {
                mma_bf16(acc[mi][ni], ahi[mi][0], ahi[mi][1], ahi[mi][2], ahi[mi][3], B0.x, B1.x);
                mma_bf16(acc[mi][ni], ahi[mi][0], ahi[mi][1], ahi[mi][2], ahi[mi][3], B0.y, B1.y);
                mma_bf16(acc[mi][ni], alo[mi][0], alo[mi][1], alo[mi][2], alo[mi][3], B0.x, B1.x);
            }
        }
    }
    #pragma unroll
    for (int mi = 0; mi < 2; ++mi) {
        int vl = v0 + r0 + 16 * mi + g, vh = vl + 8;
        #pragma unroll
        for (int ni = 0; ni < 8; ++ni) {
            int cc = n0 + 8 * ni + 2 * t;
            float ba = b1[cc], bb = b1[cc + 1];
            if (vl < N_CNT) {
                float2 o = {acc[mi][ni][0] + ba, acc[mi][ni][1] + bb};
                *(float2*)(g_hw + (size_t)vl * 128 + cc) = o;
            }
            if (vh < N_CNT) {
                float2 o = {acc[mi][ni][2] + ba, acc[mi][ni][3] + bb};
                *(float2*)(g_hw + (size_t)vh * 128 + cc) = o;
            }
        }
    }
}

// ---------------- fused edge MLP (bf16x3, K-split) + scatter -------------------
// 128 edges / 256 threads (8 warps), occupancy 2 (smem ~108.5KB).
// GEMM1-edge: hid = relu(hW[row] + ea @ W1bot); K=64, W fragments from global.
// GEMM2: out = hid @ W2 + b2; hid round-trips through smem split.
#define LDEA 36
#define LDHD 68
#define SMEM_MLP_BYTES (128 * LDEA * 8 + 128 * LDHD * 8 + 3 * 128 * 4 + 128 * 4)

__global__ void __launch_bounds__(256, 2)
k_mlp(const float* __restrict__ edge_attr,
      const int* __restrict__ eidx, const int* __restrict__ eb,
      const float* __restrict__ b2, int layer) {
    extern __shared__ char smem[];
    uint2* sEA  = (uint2*)smem;                          // [128][36]
    uint2* sHID = (uint2*)(smem + 128 * LDEA * 8);       // [128][68]
    int* sRow = (int*)(smem + 128 * LDEA * 8 + 128 * LDHD * 8);
    int* sCol = sRow + 128;
    int* sGB  = sCol + 128;
    float* sGE = (float*)(sGB + 128);                    // [2][64]

    const float* ea_in = (layer == 0) ? edge_attr : g_ea;
    float* geout = g_gesum + (layer + 1) * NGR * 64;
    const uint2* pw1 = g_W1t + layer * 128 * 64;
    const uint2* pw2 = g_W2t + layer * 64 * 64;

    const int tid = threadIdx.x;
    const int e0 = blockIdx.x * TE;

    if (tid < 128) { sRow[tid] = eidx[e0 + tid]; sGE[tid] = 0.f; }
    else {
        int u = tid - 128;
        sCol[u] = eidx[E_CNT + e0 + u];
        sGB[u] = eb[e0 + u];
    }
    // gather ea + split -> sEA
    #pragma unroll
    for (int i = 0; i < 8; ++i) {
        int f = tid + i * 256;                 // 2048 float4 = 128 x 16
        int e = f >> 4, c4 = f & 15;
        float4 x = *(const float4*)(ea_in + (size_t)(e0 + e) * 64 + c4 * 4);
        uint2 w0 = splitpack2(x.x, x.y), w1 = splitpack2(x.z, x.w);
        uint4 pk = {w0.x, w0.y, w1.x, w1.y};
        *(uint4*)&sEA[e * LDEA + c4 * 2] = pk;
    }
    __syncthreads();

    const int wid = tid >> 5, lane = tid & 31;
    const int g = lane >> 2, t = lane & 3;
    const int r0 = (wid & 3) * 32;

    // ---- GEMM1-edge: acc = ea @ W1bot (K=64), tiles 32x64
    const int n0 = (wid >> 2) * 64;
    float acc[2][8][4];
    #pragma unroll
    for (int mi = 0; mi < 2; ++mi)
        #pragma unroll
        for (int ni = 0; ni < 8; ++ni)
            #pragma unroll
            for (int q = 0; q < 4; ++q) acc[mi][ni][q] = 0.f;

    #pragma unroll
    for (int ks = 0; ks < 4; ++ks) {
        int kw = ks * 8;
        uint32_t ahi[2][4], alo[2][4];
        #pragma unroll
        for (int mi = 0; mi < 2; ++mi) {
            const uint2* ap = sEA + (r0 + 16 * mi + g) * LDEA + kw + t;
            uint2 A0 = ap[0], A1 = ap[8 * LDEA], A2 = ap[4], A3 = ap[8 * LDEA + 4];
            ahi[mi][0] = A0.x; ahi[mi][1] = A1.x; ahi[mi][2] = A2.x; ahi[mi][3] = A3.x;
            alo[mi][0] = A0.y; alo[mi][1] = A1.y; alo[mi][2] = A2.y; alo[mi][3] = A3.y;
        }
        #pragma unroll
        for (int ni = 0; ni < 8; ++ni) {
            const uint2* bp = pw1 + (n0 + 8 * ni + g) * 64 + 32 + kw + t;  // kpairs 32..63
            uint2 B0 = bp[0], B1 = bp[4];
            #pragma unroll
            for (int mi = 0; mi < 2; ++mi) {
                mma_bf16(acc[mi][ni], ahi[mi][0], ahi[mi][1], ahi[mi][2], ahi[mi][3], B0.x, B1.x);
                mma_bf16(acc[mi][ni], ahi[mi][0], ahi[mi][1], ahi[mi][2], ahi[mi][3], B0.y, B1.y);
                mma_bf16(acc[mi][ni], alo[mi][0], alo[mi][1], alo[mi][2], alo[mi][3], B0.x, B1.x);
            }
        }
    }

    // mid epilogue: hid = relu(acc + hW[row]); split -> sHID
    #pragma unroll
    for (int mi = 0; mi < 2; ++mi) {
        int el = r0 + 16 * mi + g, eh = el + 8;
        const float* hwl = g_hw + (size_t)sRow[el] * 128;
        const float* hwh = g_hw + (size_t)sRow[eh] * 128;
        #pragma unroll
        for (int ni = 0; ni < 8; ++ni) {
            int cc = n0 + 8 * ni + 2 * t;
            float2 hl = *(const float2*)(hwl + cc);
            float2 hh = *(const float2*)(hwh + cc);
            float v0 = fmaxf(acc[mi][ni][0] + hl.x, 0.f);
            float v1 = fmaxf(acc[mi][ni][1] + hl.y, 0.f);
            float v2 = fmaxf(acc[mi][ni][2] + hh.x, 0.f);
            float v3 = fmaxf(acc[mi][ni][3] + hh.y, 0.f);
            int wd = (n0 >> 1) + 4 * ni + t;
            sHID[el * LDHD + wd] = splitpack2(v0, v1);
            sHID[eh * LDHD + wd] = splitpack2(v2, v3);
        }
    }
    __syncthreads();

    // ---- GEMM2: out = hid @ W2 (K=128), tiles 32x32
    const int n2 = (wid >> 2) * 32;
    float acc2[2][4][4];
    #pragma unroll
    for (int mi = 0; mi < 2; ++mi)
        #pragma unroll
        for (int ni = 0; ni < 4; ++ni)
            #pragma unroll
            for (int q = 0; q < 4; ++q) acc2[mi][ni][q] = 0.f;

    #pragma unroll
    for (int ks = 0; ks < 8; ++ks) {
        int kw = ks * 8;
        uint32_t ahi[2][4], alo[2][4];
        #pragma unroll
        for (int mi = 0; mi < 2; ++mi) {
            const uint2* ap = sHID + (r0 + 16 * mi + g) * LDHD + kw + t;
            uint2 A0 = ap[0], A1 = ap[8 * LDHD], A2 = ap[4], A3 = ap[8 * LDHD + 4];
            ahi[mi][0] = A0.x; ahi[mi][1] = A1.x; ahi[mi][2] = A2.x; ahi[mi][3] = A3.x;
            alo[mi][0] = A0.y; alo[mi][1] = A1.y; alo[mi][2] = A2.y; alo[mi][3] = A3.y;
        }
        #pragma unroll
        for (int ni = 0; ni < 4; ++ni) {
            const uint2* bp = pw2 + (n2 + 8 * ni + g) * 64 + kw + t;
            uint2 B0 = bp[0], B1 = bp[4];
            #pragma unroll
            for (int mi = 0; mi < 2; ++mi) {
                mma_bf16(acc2[mi][ni], ahi[mi][0], ahi[mi][1], ahi[mi][2], ahi[mi][3], B0.x, B1.x);
                mma_bf16(acc2[mi][ni], ahi[mi][0], ahi[mi][1], ahi[mi][2], ahi[mi][3], B0.y, B1.y);
                mma_bf16(acc2[mi][ni], alo[mi][0], alo[mi][1], alo[mi][2], alo[mi][3], B0.x, B1.x);
            }
        }
    }

    // epilogue: +b2, store ea, node scatter, graph pool (shfl-reduced)
    int gmin = sGB[0];
    #pragma unroll
    for (int ni = 0; ni < 4; ++ni) {
        int cc = n2 + 8 * ni + 2 * t;
        float b2a = b2[cc], b2b = b2[cc + 1];
        float s0x = 0.f, s0y = 0.f, s1x = 0.f, s1y = 0.f;
        #pragma unroll
        for (int mi = 0; mi < 2; ++mi) {
            int el = r0 + 16 * mi + g, eh = el + 8;
            float2 lo = {acc2[mi][ni][0] + b2a, acc2[mi][ni][1] + b2b};
            float2 hi = {acc2[mi][ni][2] + b2a, acc2[mi][ni][3] + b2b};
            *(float2*)(g_ea + (size_t)(e0 + el) * 64 + cc) = lo;
            *(float2*)(g_ea + (size_t)(e0 + eh) * 64 + cc) = hi;
            red2(&g_hsum[(size_t)sCol[el] * 64 + cc], lo);
            red2(&g_hsum[(size_t)sCol[eh] * 64 + cc], hi);
            int sl = sGB[el] - gmin;
            if (sl == 0) { s0x += lo.x; s0y += lo.y; }
            else if (sl == 1) { s1x += lo.x; s1y += lo.y; }
            else red2(&geout[sGB[el] * 64 + cc], lo);
            sl = sGB[eh] - gmin;
            if (sl == 0) { s0x += hi.x; s0y += hi.y; }
            else if (sl == 1) { s1x += hi.x; s1y += hi.y; }
            else red2(&geout[sGB[eh] * 64 + cc], hi);
        }
        #pragma unroll
        for (int off = 16; off >= 4; off >>= 1) {
            s0x += __shfl_xor_sync(0xffffffffu, s0x, off);
            s0y += __shfl_xor_sync(0xffffffffu, s0y, off);
            s1x += __shfl_xor_sync(0xffffffffu, s1x, off);
            s1y += __shfl_xor_sync(0xffffffffu, s1y, off);
        }
        if (lane < 4) {
            if (s0x != 0.f) atomicAdd(&sGE[cc], s0x);
            if (s0y != 0.f) atomicAdd(&sGE[cc + 1], s0y);
            if (s1x != 0.f) atomicAdd(&sGE[64 + cc], s1x);
            if (s1y != 0.f) atomicAdd(&sGE[64 + cc + 1], s1y);
        }
    }
    __syncthreads();
    if (tid < 128) {     // flush SMEM graph pool
        int sl = tid >> 6, c = tid & 63;
        int gg = sGB[0] + sl;
        if (gg < NGR && sGE[tid] != 0.f) red1(&geout[gg * 64 + c], sGE[tid]);
    }
}

// ---------------- output head: one block per graph ----------------------------
__global__ void k_head(const float* __restrict__ Wo1, const float* __restrict__ bo1,
                       const float* __restrict__ Wo2, const float* __restrict__ bo2,
                       const float* __restrict__ Wo3, const float* __restrict__ bo3,
                       float* __restrict__ out) {
    __shared__ float aa[512];
    __shared__ float s1[128];
    __shared__ float s2[128];
    int g = blockIdx.x;
    int tid = threadIdx.x;
    float ninv = 1.f / fmaxf((float)g_cnt_ng[g], 1.f);
    float einv = 1.f / fmaxf((float)g_cnt_eg[g], 1.f);
    for (int i = tid; i < 512; i += 128) {
        float v;
        if (i < 256) {
            v = g_gnsum[(i >> 6) * NGR * 64 + g * 64 + (i & 63)] * ninv;
            out[g * 256 + i] = v;
        } else {
            int c = i - 256;
            v = g_gesum[(c >> 6) * NGR * 64 + g * 64 + (c & 63)] * einv;
            out[4096 + g * 256 + c] = v;
        }
        aa[i] = v;
    }
    __syncthreads();
    {
        float s = bo1[tid];
        for (int k = 0; k < 512; ++k) s = fmaf(aa[k], Wo1[k * 128 + tid], s);
        s1[tid] = fmaxf(s, 0.f);
    }
    __syncthreads();
    {
        float s = bo2[tid];
        for (int k = 0; k < 128; ++k) s = fmaf(s1[k], Wo2[k * 128 + tid], s);
        s2[tid] = fmaxf(s, 0.f);
    }
    __syncthreads();
    if (tid < 32) {
        float s = bo3[tid];
        for (int k = 0; k < 128; ++k) s = fmaf(s2[k], Wo3[k * 32 + tid], s);
        out[8192 + g * 32 + tid] = s;
    }
}

// ---------------- launcher ----------------------------------------------------
extern "C" void kernel_launch(void* const* d_in, const int* in_sizes, int n_in,
                              void* d_out, int out_size) {
    const float* edge_attr = (const float*)d_in[1];
    const int*   eidx      = (const int*)d_in[3];
    const int*   batch     = (const int*)d_in[4];
    const int*   eb        = (const int*)d_in[5];
    const float* W1s       = (const float*)d_in[6];
    const float* b1s       = (const float*)d_in[7];
    const float* W2s       = (const float*)d_in[8];
    const float* b2s       = (const float*)d_in[9];
    const float* Wo1       = (const float*)d_in[10];
    const float* bo1       = (const float*)d_in[11];
    const float* Wo2       = (const float*)d_in[12];
    const float* bo2       = (const float*)d_in[13];
    const float* Wo3       = (const float*)d_in[14];
    const float* bo3       = (const float*)d_in[15];
    float* out = (float*)d_out;

    cudaFuncSetAttribute((const void*)k_mlp,
                         cudaFuncAttributeMaxDynamicSharedMemorySize,
                         SMEM_MLP_BYTES);

    k_init<<<2048, 256>>>();
    k_wprep<<<(NLAY * 128 * 64 + NLAY * 64 * 64 + 255) / 256, 256>>>(W1s, W2s);
    k_node_cnt<<<(N_CNT + 255) / 256, 256>>>(batch);
    k_pool0<<<E_CNT / 64, 256>>>(edge_attr, eidx, eb);
    k_finalize<<<N_CNT / 16, 256>>>(0, batch);

    for (int l = 0; l < NLAY; ++l) {
        k_hw<<<(N_CNT + 127) / 128, 256>>>(b1s + l * 128, l);
        k_mlp<<<E_CNT / TE, 256, SMEM_MLP_BYTES>>>(
            edge_attr, eidx, eb, b2s + l * 64, l);
        k_finalize<<<N_CNT / 16, 256>>>(l + 1, batch);
    }

    k_head<<<NGR, 128>>>(Wo1, bo1, Wo2, bo2, Wo3, bo3, out);
}